// round 15
// baseline (speedup 1.0000x reference)
#include <cuda_runtime.h>
#include <cuda_fp16.h>
#include <cstdint>

// ---------------------------------------------------------------------------
// Problem constants
// ---------------------------------------------------------------------------
#define CIN     512
#define COUT    512
#define LIN     4096
#define KT      7
#define OUTL    4090
#define BATCH   4

// Tiling: CTA = 256 (d) x 128 (o). K-step = 64 (32 c x 2 taps), 4 phases per
// c-chunk (last is K=32), 64 steps. 256 threads, 8 warps (4m x 2n), 64x64.
#define BM      256
#define BN      128
#define BK      32
#define THREADS 256

// SMEM. A rows (d): 144B stride (9x16B -> bank r mod 8, conflict-free ldsm).
// B rows (kappa): 128 o-halves = 256B data, 272B stride (17x16B -> bank
// (r + c) mod 8, conflict-free trans-ldsm).
#define AROW    144
#define ASTG    (BM * AROW)        // 36864
#define BROW    272
#define BSTG    (64 * BROW)        // 17408

#define A_OFF   0                  // 3 * ASTG = 110592
#define B_OFF   110592             // 3 * BSTG = 52224
#define SMEM_TOTAL 162816

// ---------------------------------------------------------------------------
// Scratch (no allocations allowed -> __device__ globals)
// ---------------------------------------------------------------------------
__device__ __half g_wh[(size_t)KT * COUT * CIN];            // [k][d][c] fp16
__device__ __half g_samp[(size_t)BATCH * KT * CIN * 4096];  // [b][k][c][o] fp16
__device__ float  g_g0[(size_t)BATCH * 4096 * KT];
__device__ float  g_g1[(size_t)BATCH * 4096 * KT];
__device__ int    g_j0[(size_t)BATCH * 4096 * KT];

// ---------------------------------------------------------------------------
// Helpers
// ---------------------------------------------------------------------------
__device__ __forceinline__ uint32_t smem_u32(const void* p) {
    uint32_t a;
    asm("{ .reg .u64 t; cvta.to.shared.u64 t, %1; cvt.u32.u64 %0, t; }" : "=r"(a) : "l"(p));
    return a;
}
__device__ __forceinline__ void cp16(uint32_t dst, const void* src) {
    asm volatile("cp.async.cg.shared.global [%0], [%1], 16;" :: "r"(dst), "l"(src));
}
#define CP_COMMIT() asm volatile("cp.async.commit_group;" ::: "memory")
#define CP_WAIT(N)  asm volatile("cp.async.wait_group %0;" :: "n"(N) : "memory")

__device__ __forceinline__ void ldsm4(uint32_t& r0, uint32_t& r1, uint32_t& r2,
                                      uint32_t& r3, uint32_t addr) {
    asm volatile("ldmatrix.sync.aligned.m8n8.x4.shared.b16 {%0,%1,%2,%3}, [%4];"
                 : "=r"(r0), "=r"(r1), "=r"(r2), "=r"(r3) : "r"(addr));
}
__device__ __forceinline__ void ldsm4t(uint32_t& r0, uint32_t& r1, uint32_t& r2,
                                       uint32_t& r3, uint32_t addr) {
    asm volatile("ldmatrix.sync.aligned.m8n8.x4.trans.shared.b16 {%0,%1,%2,%3}, [%4];"
                 : "=r"(r0), "=r"(r1), "=r"(r2), "=r"(r3) : "r"(addr));
}
__device__ __forceinline__ void mma_f16(float c[4], const uint32_t a[4],
                                        uint32_t b0, uint32_t b1) {
    asm volatile(
        "mma.sync.aligned.m16n8k16.row.col.f32.f16.f16.f32 "
        "{%0,%1,%2,%3}, {%4,%5,%6,%7}, {%8,%9}, {%0,%1,%2,%3};\n"
        : "+f"(c[0]), "+f"(c[1]), "+f"(c[2]), "+f"(c[3])
        : "r"(a[0]), "r"(a[1]), "r"(a[2]), "r"(a[3]), "r"(b0), "r"(b1));
}

// ---------------------------------------------------------------------------
// Prep: blocks [0,896) weight transpose; blocks [896,1344) gather params.
// ---------------------------------------------------------------------------
__global__ void prep_all(const float* __restrict__ w, const float* __restrict__ off) {
    if (blockIdx.x < 896) {
        int i = blockIdx.x * 256 + threadIdx.x;
        int c0 = (i * 8) & 511;
        int d  = ((i * 8) >> 9) & 511;
        int k  = (i * 8) / (COUT * CIN);
        const float* src = w + ((size_t)d * CIN + c0) * KT + k;
        __half h[8];
#pragma unroll
        for (int q = 0; q < 8; ++q) h[q] = __float2half(src[q * KT]);
        *reinterpret_cast<uint4*>(g_wh + ((size_t)k * COUT + d) * CIN + c0)
            = *reinterpret_cast<const uint4*>(h);
    } else {
        int i = (blockIdx.x - 896) * 256 + threadIdx.x;
        int k = i % KT;
        int o = (i / KT) & 4095;
        int b = i / (KT * 4096);
        float gg0 = 0.f, gg1 = 0.f;
        int j0 = 0;
        if (o < OUTL) {
            float T = (float)(o + k) + off[((size_t)b * OUTL + o) * KT + k];
            T = fmaxf(T, (float)o);
            T = fminf(T, (float)(o + (KT - 1)));
            int U0 = (int)floorf(T);
            if (U0 < 0) U0 = 0;
            if (U0 > LIN - 2) U0 = LIN - 2;
            gg0 = fmaxf(0.f, 1.f - fabsf((float)U0 - T));
            gg1 = fmaxf(0.f, 1.f - fabsf((float)(U0 + 1) - T));
            j0 = U0 - o;
        }
        g_j0[i] = j0;
        g_g0[i] = gg0;
        g_g1[i] = gg1;
    }
}

// ---------------------------------------------------------------------------
// samp materialization: g_samp[b][k][c][o] = g0*x[c][o+j] + g1*x[c][o+j+1]
// (fp32 interp, one rounding to fp16). Block = (o-tile of 64, batch).
// ---------------------------------------------------------------------------
__global__ __launch_bounds__(256)
void samp_build(const float* __restrict__ x) {
    __shared__ float xs[32][72];
    __shared__ float sg0[KT][64], sg1[KT][64];
    __shared__ int   sj[KT][64];
    const int tid = threadIdx.x;
    const int o0  = blockIdx.x * 64;
    const int b   = blockIdx.y;

    for (int i = tid; i < KT * 64; i += 256) {
        int k = i >> 6, o = i & 63;
        int gi = ((b * 4096) + o0 + o) * KT + k;
        sj[k][o]  = g_j0[gi];
        sg0[k][o] = g_g0[gi];
        sg1[k][o] = g_g1[gi];
    }

    for (int c0 = 0; c0 < CIN; c0 += 32) {
        __syncthreads();   // params (first iter) / previous chunk consumers
        for (int i = tid; i < 32 * 72; i += 256) {
            int r = i / 72, t = i - r * 72;
            int gt = o0 + t;
            xs[r][t] = (gt < LIN) ? x[((size_t)(b * CIN + c0 + r)) * LIN + gt] : 0.f;
        }
        __syncthreads();
#pragma unroll
        for (int it = 0; it < 28; ++it) {
            int i = tid + it * 256;            // 224 rows x 32 o-pairs
            int row = i >> 5, pr = i & 31;
            int c = row / 7, k = row - c * 7;
            int oA = pr * 2, oB = oA + 1;
            int jA = sj[k][oA], jB = sj[k][oB];
            float v0 = sg0[k][oA] * xs[c][oA + jA] + sg1[k][oA] * xs[c][oA + jA + 1];
            float v1 = sg0[k][oB] * xs[c][oB + jB] + sg1[k][oB] * xs[c][oB + jB + 1];
            *reinterpret_cast<__half2*>(
                g_samp + ((size_t)(b * KT + k) * CIN + c0 + c) * 4096 + o0 + oA)
                = __floats2half2_rn(v0, v1);
        }
    }
}

// ---------------------------------------------------------------------------
// Operand loaders (cp.async)
// ---------------------------------------------------------------------------
__device__ __forceinline__ void load_A(uint32_t dbase, int kbase, int kcount,
                                       int c0, int d0, int tid) {
    if (kcount == 2) {
#pragma unroll
        for (int it = 0; it < 8; ++it) {
            int i = tid + it * THREADS;
            int r = i >> 3, ch = i & 7;
            int tap = kbase + (ch >> 2);
            cp16(dbase + r * AROW + ch * 16,
                 g_wh + ((size_t)tap * COUT + d0 + r) * CIN + c0 + (ch & 3) * 8);
        }
    } else {
#pragma unroll
        for (int it = 0; it < 4; ++it) {
            int i = tid + it * THREADS;
            int r = i >> 2, ch = i & 3;
            cp16(dbase + r * AROW + ch * 16,
                 g_wh + ((size_t)kbase * COUT + d0 + r) * CIN + c0 + ch * 8);
        }
    }
}

__device__ __forceinline__ void load_B(uint32_t dbase, int kbase, int kcount,
                                       int c0, int o0, int b, int tid) {
#pragma unroll
    for (int it = 0; it < 4; ++it) {
        if (it >= kcount * 2) break;
        int i = tid + it * THREADS;
        int r = i >> 4, q = i & 15;            // r = kappa row, q = 8-half col
        int tap = kbase + (r >> 5), cr = r & 31;
        cp16(dbase + r * BROW + q * 16,
             g_samp + ((size_t)(b * KT + tap) * CIN + c0 + cr) * 4096 + o0 + q * 8);
    }
}

// ---------------------------------------------------------------------------
// Main: pure fp16 GEMM over materialized samp. 3-stage A and B rings.
// ---------------------------------------------------------------------------
__global__ __launch_bounds__(THREADS, 1)
void deform_mma(const float* __restrict__ bias, float* __restrict__ out) {
    extern __shared__ char smem[];
    const uint32_t sbase = smem_u32(smem);

    const int tid  = threadIdx.x;
    const int lane = tid & 31;
    const int wid  = tid >> 5;
    const int o0 = blockIdx.x * BN;
    const int d0 = blockIdx.y * BM;
    const int b  = blockIdx.z;

    const int m_base = (wid & 3) * 64;
    const int n_base = (wid >> 2) * 64;

    // ---- prologue: stage 0 (taps 0,1) and stage 1 (taps 2,3), chunk 0 ----
    load_A(sbase + A_OFF, 0, 2, 0, d0, tid);
    load_B(sbase + B_OFF, 0, 2, 0, o0, b, tid);
    CP_COMMIT();
    load_A(sbase + A_OFF + ASTG, 2, 2, 0, d0, tid);
    load_B(sbase + B_OFF + BSTG, 2, 2, 0, o0, b, tid);
    CP_COMMIT();

    float acc[4][8][4];
#pragma unroll
    for (int mi = 0; mi < 4; ++mi)
#pragma unroll
        for (int ni = 0; ni < 8; ++ni)
#pragma unroll
            for (int q = 0; q < 4; ++q) acc[mi][ni][q] = 0.f;

    // ---- mainloop: 64 steps (16 c-chunks x 4 tap phases: 01,23,45,6) ----
    for (int cc = 0; cc < 16; ++cc) {
#pragma unroll
        for (int p = 0; p < 4; ++p) {
            const int s = cc * 4 + p;
            CP_WAIT(1);        // forces the group carrying stage s
            __syncthreads();   // all warps done reading stage s-1; s visible

            // prefetch stage s+2
            {
                const int t = s + 2;
                if (t < 64) {
                    const int pt = t & 3, ct = t >> 2;
                    const int kc = (pt < 3) ? 2 : 1;
                    load_A(sbase + A_OFF + (t % 3) * ASTG, 2 * pt, kc, ct * BK, d0, tid);
                    load_B(sbase + B_OFF + (t % 3) * BSTG, 2 * pt, kc, ct * BK, o0, b, tid);
                }
            }
            CP_COMMIT();

            // ---- mma on stage s ----
            {
                const uint32_t abase = sbase + A_OFF + (s % 3) * ASTG;
                const uint32_t bbase = sbase + B_OFF + (s % 3) * BSTG;
                const int kkmax = (p < 3) ? 4 : 2;
#pragma unroll
                for (int kk = 0; kk < 4; ++kk) {
                    if (kk >= kkmax) break;
                    uint32_t afr[4][4];
#pragma unroll
                    for (int mi = 0; mi < 4; ++mi) {
                        uint32_t addr = abase
                            + (uint32_t)(m_base + mi * 16 + (lane & 15)) * AROW
                            + kk * 32 + (lane & 16);
                        ldsm4(afr[mi][0], afr[mi][1], afr[mi][2], afr[mi][3], addr);
                    }
                    uint32_t bfr[8][2];
#pragma unroll
                    for (int nb = 0; nb < 4; ++nb) {
                        uint32_t addr = bbase
                            + (uint32_t)(kk * 16 + (lane & 15)) * BROW
                            + (uint32_t)(n_base + nb * 16 + ((lane >> 4) << 3)) * 2;
                        ldsm4t(bfr[2 * nb][0], bfr[2 * nb][1],
                               bfr[2 * nb + 1][0], bfr[2 * nb + 1][1], addr);
                    }
#pragma unroll
                    for (int ni = 0; ni < 8; ++ni) {
#pragma unroll
                        for (int mi = 0; mi < 4; ++mi)
                            mma_f16(acc[mi][ni], afr[mi], bfr[ni][0], bfr[ni][1]);
                    }
                }
            }
        }
    }

    // ---- epilogue: bias add + store ----
    const int qg = lane >> 2, tq = lane & 3;
#pragma unroll
    for (int mi = 0; mi < 4; ++mi) {
        int d = d0 + m_base + mi * 16 + qg;
        float bz0 = bias[d];
        float bz1 = bias[d + 8];
        size_t row0 = ((size_t)b * COUT + d) * OUTL;
        size_t row1 = row0 + (size_t)8 * OUTL;
#pragma unroll
        for (int ni = 0; ni < 8; ++ni) {
            int col = o0 + n_base + ni * 8 + 2 * tq;
            if (col < OUTL) {   // col even, OUTL even => col+1 < OUTL too
                float2 v0 = make_float2(acc[mi][ni][0] + bz0, acc[mi][ni][1] + bz0);
                float2 v1 = make_float2(acc[mi][ni][2] + bz1, acc[mi][ni][3] + bz1);
                *reinterpret_cast<float2*>(out + row0 + col) = v0;
                *reinterpret_cast<float2*>(out + row1 + col) = v1;
            }
        }
    }
}

// ---------------------------------------------------------------------------
extern "C" void kernel_launch(void* const* d_in, const int* in_sizes, int n_in,
                              void* d_out, int out_size) {
    const float* x    = (const float*)d_in[0];
    const float* off  = (const float*)d_in[1];
    const float* w    = (const float*)d_in[2];
    const float* bias = (const float*)d_in[3];
    float* out = (float*)d_out;

    prep_all<<<1344, 256>>>(w, off);

    dim3 sgrid(64, BATCH);                    // 64 o-tiles x 4 batches
    samp_build<<<sgrid, 256>>>(x);

    cudaFuncSetAttribute(deform_mma, cudaFuncAttributeMaxDynamicSharedMemorySize,
                         SMEM_TOTAL);
    dim3 grid(4096 / BN, COUT / BM, BATCH);   // 32 x 2 x 4 = 256 CTAs
    deform_mma<<<grid, THREADS, SMEM_TOTAL>>>(bias, out);
}